// round 15
// baseline (speedup 1.0000x reference)
#include <cuda_runtime.h>
#include <cuda_fp16.h>
#include <cstdint>
#include <cstddef>

#define DIM_K 4096      // in_features
#define DIM_N 4096      // out_features
#define DIM_M 8192      // B*S

// ---------------- scratch (static device arrays; no allocation) ----------------
__device__ __align__(256) float g_part[32 * DIM_K];      // column-norm partials (32 row groups)
__device__ __align__(256) float g_mask[DIM_K];           // 1.0 = binarized column
__device__ float g_nbin;
__device__ __align__(256) __half g_xh[(size_t)DIM_M * DIM_K];   // fp16 x
__device__ __align__(256) __half g_wh[(size_t)DIM_N * DIM_K];   // fp16 w_bin

__device__ __forceinline__ uint32_t smem_u32(const void* p) {
    uint32_t a;
    asm("{ .reg .u64 t; cvta.to.shared.u64 t, %1; cvt.u32.u64 %0, t; }" : "=r"(a) : "l"(p));
    return a;
}

// ================= preprocessing (unchanged) =================

// Column L1-norm partials: 32 row groups x 128 rows, ascending add order.
__global__ void k_colpart(const float* __restrict__ w) {
    int j  = blockIdx.x * 256 + threadIdx.x;
    int i0 = blockIdx.y * 128;
    const float* p = w + (size_t)i0 * DIM_K + j;
    float s = 0.f;
#pragma unroll 16
    for (int i = 0; i < 128; ++i) s += fabsf(p[(size_t)i * DIM_K]);
    g_part[blockIdx.y * DIM_K + j] = s;
}

// Fused: block 0 = partial reduction + bitonic sort + quantiles + mask + n_bin;
// blocks 1..2048 = x -> fp16 conversion (idle SMs do useful work).
__global__ void k_quantx(const float* __restrict__ x) {
    int t = threadIdx.x;  // 1024 threads

    if (blockIdx.x != 0) {
        size_t i0 = (((size_t)(blockIdx.x - 1) * 1024 + t) * 16);
#pragma unroll
        for (int u = 0; u < 4; ++u) {
            float4 v = *(const float4*)(x + i0 + u * 4);
            *(__half2*)(g_xh + i0 + u * 4)     = __floats2half2_rn(v.x, v.y);
            *(__half2*)(g_xh + i0 + u * 4 + 2) = __floats2half2_rn(v.z, v.w);
        }
        return;
    }

    __shared__ float s_sorted[DIM_K];
    __shared__ float s_lo, s_hi;
    __shared__ int s_cnt;
    float val[4];

#pragma unroll
    for (int c = 0; c < 4; ++c) {
        int j = c * 1024 + t;
        float v = 0.f;
#pragma unroll
        for (int p = 0; p < 32; ++p) v += g_part[p * DIM_K + j];
        val[c] = v;
        s_sorted[j] = v;
    }
    if (t == 0) s_cnt = 0;
    __syncthreads();

    for (int k = 2; k <= DIM_K; k <<= 1) {
        for (int jj = k >> 1; jj > 0; jj >>= 1) {
#pragma unroll
            for (int c = 0; c < 4; ++c) {
                int i = c * 1024 + t;
                int ixj = i ^ jj;
                if (ixj > i) {
                    float a = s_sorted[i], b = s_sorted[ixj];
                    bool up = ((i & k) == 0);
                    if ((a > b) == up) { s_sorted[i] = b; s_sorted[ixj] = a; }
                }
            }
            __syncthreads();
        }
    }

    if (t == 0) {
        // jnp.quantile 'linear': 0.05*4095 = 204.75; 0.95*4095 = 3890.25
        s_lo = s_sorted[204]  + 0.75f * (s_sorted[205]  - s_sorted[204]);
        s_hi = s_sorted[3890] + 0.25f * (s_sorted[3891] - s_sorted[3890]);
    }
    __syncthreads();

    int local = 0;
#pragma unroll
    for (int c = 0; c < 4; ++c) {
        int j = c * 1024 + t;
        float v = val[c];
        bool band = (v > s_lo) && (v < s_hi);   // middle band
        float m = band ? 0.f : 1.f;             // binarized = ~band
        g_mask[j] = m;
        local += (int)m;
    }
    atomicAdd(&s_cnt, local);
    __syncthreads();
    if (t == 0) g_nbin = (float)s_cnt;
}

// Per w-row: scale = sum(|w|*mask)/n_bin; o = mask ? w*scale : w; emit fp16.
__global__ void k_wbinh(const float* __restrict__ w) {
    __shared__ float red[256];
    __shared__ float s_scale;
    int r = blockIdx.x, t = threadIdx.x;
    const float* wr = w + (size_t)r * DIM_K;

    float4 v4[4];
#pragma unroll
    for (int c = 0; c < 4; ++c) v4[c] = *(const float4*)(wr + t * 4 + c * 1024);

    float s = 0.f;
#pragma unroll
    for (int c = 0; c < 4; ++c) {
        const float* f = (const float*)&v4[c];
#pragma unroll
        for (int e = 0; e < 4; ++e) s += fabsf(f[e]) * g_mask[t * 4 + c * 1024 + e];
    }
    red[t] = s; __syncthreads();
    for (int o = 128; o > 0; o >>= 1) { if (t < o) red[t] += red[t + o]; __syncthreads(); }
    if (t == 0) s_scale = red[0] / g_nbin;
    __syncthreads();
    float scale = s_scale;

#pragma unroll
    for (int c = 0; c < 4; ++c) {
        const float* f = (const float*)&v4[c];
        float o[4];
#pragma unroll
        for (int e = 0; e < 4; ++e) {
            int j = t * 4 + c * 1024 + e;
            o[e] = (g_mask[j] != 0.f) ? f[e] * scale : f[e];
        }
        size_t idx = (size_t)r * DIM_K + t * 4 + c * 1024;
        *(__half2*)(g_wh + idx)     = __floats2half2_rn(o[0], o[1]);
        *(__half2*)(g_wh + idx + 2) = __floats2half2_rn(o[2], o[3]);
    }
}

// ================= GEMM: out = x @ w_bin^T + bias (fp16 mma, f32 accum) =================
// CTA 128x128, 4 warps (2M x 2N), warp tile 64x64, BK=64 fp16 (=128B rows, SW128
// swizzle), 3-stage cp.async (wait_group 0), 2 CTAs/SM, register fragments
// double-buffered ACROSS kt boundaries (ks0 of kt+1 prefetched during kt's ks3).
#define BM 128
#define BN 128
#define BK 64
#define KTILES (DIM_K / BK)         // 64
#define STAGES 3
#define A_BYTES 16384               // 128 rows x 128B
#define B_BYTES 16384
#define STAGE_BYTES (A_BYTES + B_BYTES)
#define GEMM_SMEM (STAGES * STAGE_BYTES)

__device__ __forceinline__ void cp16(uint32_t dst, const void* src) {
    asm volatile("cp.async.cg.shared.global [%0], [%1], 16;" :: "r"(dst), "l"(src));
}
__device__ __forceinline__ void ldm_x4(uint32_t* r, uint32_t addr) {
    asm volatile("ldmatrix.sync.aligned.m8n8.x4.shared.b16 {%0,%1,%2,%3}, [%4];"
                 : "=r"(r[0]), "=r"(r[1]), "=r"(r[2]), "=r"(r[3]) : "r"(addr));
}
__device__ __forceinline__ void mma_f16(float* c, const uint32_t* a,
                                        uint32_t b0, uint32_t b1) {
    asm volatile(
        "mma.sync.aligned.m16n8k16.row.col.f32.f16.f16.f32 "
        "{%0,%1,%2,%3}, {%4,%5,%6,%7}, {%8,%9}, {%0,%1,%2,%3};"
        : "+f"(c[0]), "+f"(c[1]), "+f"(c[2]), "+f"(c[3])
        : "r"(a[0]), "r"(a[1]), "r"(a[2]), "r"(a[3]), "r"(b0), "r"(b1));
}

__global__ void __launch_bounds__(128, 2) k_gemm(
    const float* __restrict__ bias, float* __restrict__ out)
{
    extern __shared__ char smem[];
    const uint32_t sb = smem_u32(smem);
    const int tid = threadIdx.x;
    const int wid = tid >> 5;
    const int lane = tid & 31;
    const int warp_m = wid & 1;    // 0..1 -> M offset 64
    const int warp_n = wid >> 1;   // 0..1 -> N offset 64
    const int ntile = blockIdx.x;
    const int mtile = blockIdx.y;

    const __half* gA = g_xh + (size_t)mtile * BM * DIM_K;
    const __half* gB = g_wh + (size_t)ntile * BN * DIM_K;

    // loaders: 8 threads per 128B smem row (16B each); 128 threads -> 16 rows/pass,
    // 8 passes for each of A and B (128 rows each).
    const int lrow = tid >> 3;          // 0..15
    const int lc   = tid & 7;           // 16B chunk in row
    uint32_t swz[8];
#pragma unroll
    for (int p = 0; p < 8; ++p) {
        int row = lrow + p * 16;
        swz[p] = (uint32_t)(row * 128 + ((lc * 16) ^ ((row & 7) << 4)));
    }

    // ldmatrix lane addressing
    const uint32_t sx = (uint32_t)((lane & 7) << 4);
    const int arow = warp_m * 64 + (lane & 15);                          // + mt*16
    const uint32_t acol16 = (lane & 16) ? 16u : 0u;
    const int brow = warp_n * 64 + (lane & 7) + ((lane & 16) ? 8 : 0);   // + h*16
    const uint32_t bcol16 = (lane & 8) ? 16u : 0u;

    float acc[4][8][4];
#pragma unroll
    for (int i = 0; i < 4; ++i)
#pragma unroll
        for (int j = 0; j < 8; ++j)
#pragma unroll
            for (int k = 0; k < 4; ++k) acc[i][j][k] = 0.f;

    auto load_stage = [&](int s, int kt) {
        uint32_t sA = sb + s * STAGE_BYTES;
        uint32_t sB = sA + A_BYTES;
#pragma unroll
        for (int p = 0; p < 8; ++p) {
            int row = lrow + p * 16;
            cp16(sA + swz[p], gA + (size_t)row * DIM_K + kt * BK + lc * 8);
        }
#pragma unroll
        for (int p = 0; p < 8; ++p) {
            int row = lrow + p * 16;
            cp16(sB + swz[p], gB + (size_t)row * DIM_K + kt * BK + lc * 8);
        }
    };

    // fragment double buffers
    uint32_t afr[2][16], bfr[2][16];
    auto load_frags = [&](int buf, uint32_t sA, uint32_t sB, int ks) {
        const uint32_t bcol = ((uint32_t)(ks * 32) + bcol16);
        const uint32_t acol = ((uint32_t)(ks * 32) + acol16);
#pragma unroll
        for (int h = 0; h < 4; ++h)
            ldm_x4(bfr[buf] + 4 * h, sB + (uint32_t)((brow + h * 16) * 128) + (bcol ^ sx));
#pragma unroll
        for (int mt = 0; mt < 4; ++mt)
            ldm_x4(afr[buf] + 4 * mt, sA + (uint32_t)((arow + mt * 16) * 128) + (acol ^ sx));
    };

    // ---- prologue: prime stages 0 and 1 ----
    load_stage(0, 0);
    asm volatile("cp.async.commit_group;" ::: "memory");
    load_stage(1, 1);
    asm volatile("cp.async.commit_group;" ::: "memory");

    for (int kt = 0; kt < KTILES; ++kt) {
        asm volatile("cp.async.wait_group 0;" ::: "memory");   // stages kt AND kt+1 resident
        __syncthreads();

        const int s = kt % STAGES;
        const uint32_t sA = sb + s * STAGE_BYTES;
        const uint32_t sB = sA + A_BYTES;
        const int sn = (kt + 1) % STAGES;
        const uint32_t sAn = sb + sn * STAGE_BYTES;
        const uint32_t sBn = sAn + A_BYTES;

        if (kt == 0) load_frags(0, sA, sB, 0);   // first tile only; thereafter carried

        if (kt + 2 < KTILES) {
            load_stage((kt + 2) % STAGES, kt + 2);
            asm volatile("cp.async.commit_group;" ::: "memory");
        }

#pragma unroll
        for (int ks = 0; ks < 4; ++ks) {           // 4 x k16 = BK 64
            const int cur = ks & 1;
            if (ks < 3)
                load_frags(cur ^ 1, sA, sB, ks + 1);
            else if (kt + 1 < KTILES)
                load_frags(cur ^ 1, sAn, sBn, 0);  // ks0 of NEXT kt (stage resident)
#pragma unroll
            for (int mt = 0; mt < 4; ++mt)
#pragma unroll
                for (int nt = 0; nt < 8; ++nt)
                    mma_f16(acc[mt][nt], afr[cur] + 4 * mt,
                            bfr[cur][2 * nt], bfr[cur][2 * nt + 1]);
        }
    }

    // ---- epilogue: add bias, store fp32 ----
    const int obase_n = ntile * BN + warp_n * 64;
    float bv0[8], bv1[8];
#pragma unroll
    for (int nt = 0; nt < 8; ++nt) {
        int col = obase_n + nt * 8 + (lane & 3) * 2;
        bv0[nt] = __ldg(bias + col);
        bv1[nt] = __ldg(bias + col + 1);
    }
#pragma unroll
    for (int mt = 0; mt < 4; ++mt) {
        int row0 = mtile * BM + warp_m * 64 + mt * 16 + (lane >> 2);
#pragma unroll
        for (int nt = 0; nt < 8; ++nt) {
            int col = obase_n + nt * 8 + (lane & 3) * 2;
            float2 o0 = make_float2(acc[mt][nt][0] + bv0[nt], acc[mt][nt][1] + bv1[nt]);
            float2 o1 = make_float2(acc[mt][nt][2] + bv0[nt], acc[mt][nt][3] + bv1[nt]);
            *(float2*)(out + (size_t)row0 * DIM_N + col) = o0;
            *(float2*)(out + (size_t)(row0 + 8) * DIM_N + col) = o1;
        }
    }
}

// ================= launch =================
extern "C" void kernel_launch(void* const* d_in, const int* in_sizes, int n_in,
                              void* d_out, int out_size) {
    const float* x    = (const float*)d_in[0];   // [8192, 4096]
    const float* w    = (const float*)d_in[1];   // [4096, 4096]
    const float* bias = (const float*)d_in[2];   // [4096]
    float* out = (float*)d_out;                  // [8192, 4096]

    cudaFuncSetAttribute(k_gemm, cudaFuncAttributeMaxDynamicSharedMemorySize, GEMM_SMEM);

    const int xblocks = (int)((size_t)DIM_M * DIM_K / (1024 * 16));   // 2048
    k_colpart<<<dim3(DIM_K / 256, 32), 256>>>(w);     // launch 0
    k_quantx<<<1 + xblocks, 1024>>>(x);               // launch 1 (reduce+sort + x->fp16)
    k_wbinh<<<DIM_N, 256>>>(w);                       // launch 2
    k_gemm<<<dim3(DIM_N / BN, DIM_M / BM), 128, GEMM_SMEM>>>(bias, out);  // launch 3 (ncu slot)
}

// round 16
// speedup vs baseline: 1.0378x; 1.0378x over previous
#include <cuda_runtime.h>
#include <cuda_fp16.h>
#include <cstdint>
#include <cstddef>

#define DIM_K 4096      // in_features
#define DIM_N 4096      // out_features
#define DIM_M 8192      // B*S

// ---------------- scratch (static device arrays; no allocation) ----------------
__device__ __align__(256) float g_part[32 * DIM_K];      // column-norm partials (32 row groups)
__device__ __align__(256) float g_mask[DIM_K];           // 1.0 = binarized column
__device__ float g_nbin;
__device__ __align__(256) __half g_xh[(size_t)DIM_M * DIM_K];   // fp16 x
__device__ __align__(256) __half g_wh[(size_t)DIM_N * DIM_K];   // fp16 w_bin

__device__ __forceinline__ uint32_t smem_u32(const void* p) {
    uint32_t a;
    asm("{ .reg .u64 t; cvta.to.shared.u64 t, %1; cvt.u32.u64 %0, t; }" : "=r"(a) : "l"(p));
    return a;
}

// ================= preprocessing (unchanged) =================

// Column L1-norm partials: 32 row groups x 128 rows, ascending add order.
__global__ void k_colpart(const float* __restrict__ w) {
    int j  = blockIdx.x * 256 + threadIdx.x;
    int i0 = blockIdx.y * 128;
    const float* p = w + (size_t)i0 * DIM_K + j;
    float s = 0.f;
#pragma unroll 16
    for (int i = 0; i < 128; ++i) s += fabsf(p[(size_t)i * DIM_K]);
    g_part[blockIdx.y * DIM_K + j] = s;
}

// Fused: block 0 = partial reduction + bitonic sort + quantiles + mask + n_bin;
// blocks 1..2048 = x -> fp16 conversion (idle SMs do useful work).
__global__ void k_quantx(const float* __restrict__ x) {
    int t = threadIdx.x;  // 1024 threads

    if (blockIdx.x != 0) {
        size_t i0 = (((size_t)(blockIdx.x - 1) * 1024 + t) * 16);
#pragma unroll
        for (int u = 0; u < 4; ++u) {
            float4 v = *(const float4*)(x + i0 + u * 4);
            *(__half2*)(g_xh + i0 + u * 4)     = __floats2half2_rn(v.x, v.y);
            *(__half2*)(g_xh + i0 + u * 4 + 2) = __floats2half2_rn(v.z, v.w);
        }
        return;
    }

    __shared__ float s_sorted[DIM_K];
    __shared__ float s_lo, s_hi;
    __shared__ int s_cnt;
    float val[4];

#pragma unroll
    for (int c = 0; c < 4; ++c) {
        int j = c * 1024 + t;
        float v = 0.f;
#pragma unroll
        for (int p = 0; p < 32; ++p) v += g_part[p * DIM_K + j];
        val[c] = v;
        s_sorted[j] = v;
    }
    if (t == 0) s_cnt = 0;
    __syncthreads();

    for (int k = 2; k <= DIM_K; k <<= 1) {
        for (int jj = k >> 1; jj > 0; jj >>= 1) {
#pragma unroll
            for (int c = 0; c < 4; ++c) {
                int i = c * 1024 + t;
                int ixj = i ^ jj;
                if (ixj > i) {
                    float a = s_sorted[i], b = s_sorted[ixj];
                    bool up = ((i & k) == 0);
                    if ((a > b) == up) { s_sorted[i] = b; s_sorted[ixj] = a; }
                }
            }
            __syncthreads();
        }
    }

    if (t == 0) {
        // jnp.quantile 'linear': 0.05*4095 = 204.75; 0.95*4095 = 3890.25
        s_lo = s_sorted[204]  + 0.75f * (s_sorted[205]  - s_sorted[204]);
        s_hi = s_sorted[3890] + 0.25f * (s_sorted[3891] - s_sorted[3890]);
    }
    __syncthreads();

    int local = 0;
#pragma unroll
    for (int c = 0; c < 4; ++c) {
        int j = c * 1024 + t;
        float v = val[c];
        bool band = (v > s_lo) && (v < s_hi);   // middle band
        float m = band ? 0.f : 1.f;             // binarized = ~band
        g_mask[j] = m;
        local += (int)m;
    }
    atomicAdd(&s_cnt, local);
    __syncthreads();
    if (t == 0) g_nbin = (float)s_cnt;
}

// Per w-row: scale = sum(|w|*mask)/n_bin; o = mask ? w*scale : w; emit fp16.
__global__ void k_wbinh(const float* __restrict__ w) {
    __shared__ float red[256];
    __shared__ float s_scale;
    int r = blockIdx.x, t = threadIdx.x;
    const float* wr = w + (size_t)r * DIM_K;

    float4 v4[4];
#pragma unroll
    for (int c = 0; c < 4; ++c) v4[c] = *(const float4*)(wr + t * 4 + c * 1024);

    float s = 0.f;
#pragma unroll
    for (int c = 0; c < 4; ++c) {
        const float* f = (const float*)&v4[c];
#pragma unroll
        for (int e = 0; e < 4; ++e) s += fabsf(f[e]) * g_mask[t * 4 + c * 1024 + e];
    }
    red[t] = s; __syncthreads();
    for (int o = 128; o > 0; o >>= 1) { if (t < o) red[t] += red[t + o]; __syncthreads(); }
    if (t == 0) s_scale = red[0] / g_nbin;
    __syncthreads();
    float scale = s_scale;

#pragma unroll
    for (int c = 0; c < 4; ++c) {
        const float* f = (const float*)&v4[c];
        float o[4];
#pragma unroll
        for (int e = 0; e < 4; ++e) {
            int j = t * 4 + c * 1024 + e;
            o[e] = (g_mask[j] != 0.f) ? f[e] * scale : f[e];
        }
        size_t idx = (size_t)r * DIM_K + t * 4 + c * 1024;
        *(__half2*)(g_wh + idx)     = __floats2half2_rn(o[0], o[1]);
        *(__half2*)(g_wh + idx + 2) = __floats2half2_rn(o[2], o[3]);
    }
}

// ================= GEMM: out = x @ w_bin^T + bias (fp16 mma, f32 accum) =================
// CTA 128x128, 4 warps (2M x 2N), warp tile 64x64, BK=64 fp16 (=128B rows, SW128
// swizzle), 3-stage cp.async (wait_group 1), 2 CTAs/SM, in-kt register fragment
// double buffer. [R14 structure + strength-reduced stage/pointer bookkeeping]
#define BM 128
#define BN 128
#define BK 64
#define KTILES (DIM_K / BK)         // 64
#define STAGES 3
#define A_BYTES 16384               // 128 rows x 128B
#define B_BYTES 16384
#define STAGE_BYTES (A_BYTES + B_BYTES)
#define GEMM_SMEM (STAGES * STAGE_BYTES)

__device__ __forceinline__ void cp16(uint32_t dst, const void* src) {
    asm volatile("cp.async.cg.shared.global [%0], [%1], 16;" :: "r"(dst), "l"(src));
}
__device__ __forceinline__ void ldm_x4(uint32_t* r, uint32_t addr) {
    asm volatile("ldmatrix.sync.aligned.m8n8.x4.shared.b16 {%0,%1,%2,%3}, [%4];"
                 : "=r"(r[0]), "=r"(r[1]), "=r"(r[2]), "=r"(r[3]) : "r"(addr));
}
__device__ __forceinline__ void mma_f16(float* c, const uint32_t* a,
                                        uint32_t b0, uint32_t b1) {
    asm volatile(
        "mma.sync.aligned.m16n8k16.row.col.f32.f16.f16.f32 "
        "{%0,%1,%2,%3}, {%4,%5,%6,%7}, {%8,%9}, {%0,%1,%2,%3};"
        : "+f"(c[0]), "+f"(c[1]), "+f"(c[2]), "+f"(c[3])
        : "r"(a[0]), "r"(a[1]), "r"(a[2]), "r"(a[3]), "r"(b0), "r"(b1));
}

__global__ void __launch_bounds__(128, 2) k_gemm(
    const float* __restrict__ bias, float* __restrict__ out)
{
    extern __shared__ char smem[];
    const uint32_t sb = smem_u32(smem);
    const int tid = threadIdx.x;
    const int wid = tid >> 5;
    const int lane = tid & 31;
    const int warp_m = wid & 1;    // 0..1 -> M offset 64
    const int warp_n = wid >> 1;   // 0..1 -> N offset 64
    const int ntile = blockIdx.x;
    const int mtile = blockIdx.y;

    // loaders: 8 threads per 128B smem row (16B each); 128 threads -> 16 rows/pass,
    // 8 passes for each of A and B (128 rows each).
    const int lrow = tid >> 3;          // 0..15
    const int lc   = tid & 7;           // 16B chunk in row
    uint32_t swz[8];
#pragma unroll
    for (int p = 0; p < 8; ++p) {
        int row = lrow + p * 16;
        swz[p] = (uint32_t)(row * 128 + ((lc * 16) ^ ((row & 7) << 4)));
    }

    // incrementally advanced global pointers (thread-local row assignment baked in)
    const __half* gAp = g_xh + (size_t)mtile * BM * DIM_K + (size_t)lrow * DIM_K + lc * 8;
    const __half* gBp = g_wh + (size_t)ntile * BN * DIM_K + (size_t)lrow * DIM_K + lc * 8;

    // ldmatrix lane addressing
    const uint32_t sx = (uint32_t)((lane & 7) << 4);
    const int arow = warp_m * 64 + (lane & 15);                          // + mt*16
    const uint32_t acol16 = (lane & 16) ? 16u : 0u;
    const int brow = warp_n * 64 + (lane & 7) + ((lane & 16) ? 8 : 0);   // + h*16
    const uint32_t bcol16 = (lane & 8) ? 16u : 0u;

    float acc[4][8][4];
#pragma unroll
    for (int i = 0; i < 4; ++i)
#pragma unroll
        for (int j = 0; j < 8; ++j)
#pragma unroll
            for (int k = 0; k < 4; ++k) acc[i][j][k] = 0.f;

    // prefetch-side: stage smem offset carried incrementally
    auto load_stage_at = [&](uint32_t sOff, const __half* ga, const __half* gb) {
        uint32_t sA = sb + sOff;
        uint32_t sB = sA + A_BYTES;
#pragma unroll
        for (int p = 0; p < 8; ++p)
            cp16(sA + swz[p], ga + (size_t)(p * 16) * DIM_K);
#pragma unroll
        for (int p = 0; p < 8; ++p)
            cp16(sB + swz[p], gb + (size_t)(p * 16) * DIM_K);
    };

    // fragment double buffers
    uint32_t afr[2][16], bfr[2][16];
    auto load_frags = [&](int buf, uint32_t sA, uint32_t sB, uint32_t kcol) {
        const uint32_t bcol = kcol + bcol16;
        const uint32_t acol = kcol + acol16;
#pragma unroll
        for (int h = 0; h < 4; ++h)
            ldm_x4(bfr[buf] + 4 * h, sB + (uint32_t)((brow + h * 16) * 128) + (bcol ^ sx));
#pragma unroll
        for (int mt = 0; mt < 4; ++mt)
            ldm_x4(afr[buf] + 4 * mt, sA + (uint32_t)((arow + mt * 16) * 128) + (acol ^ sx));
    };

    // ---- prologue: prime stages 0 and 1 ----
    load_stage_at(0, gAp, gBp);
    asm volatile("cp.async.commit_group;" ::: "memory");
    load_stage_at(STAGE_BYTES, gAp + BK, gBp + BK);
    asm volatile("cp.async.commit_group;" ::: "memory");
    gAp += 2 * BK; gBp += 2 * BK;                 // next prefetch kt = 2

    uint32_t csOff = 0;                           // compute stage smem offset
    uint32_t psOff = 2 * STAGE_BYTES;             // prefetch stage smem offset

    for (int kt = 0; kt < KTILES; ++kt) {
        asm volatile("cp.async.wait_group 1;" ::: "memory");
        __syncthreads();

        const uint32_t sA = sb + csOff;
        const uint32_t sB = sA + A_BYTES;

        // start ks=0 fragment loads immediately (overlaps cp.async issue below)
        load_frags(0, sA, sB, 0);

        if (kt + STAGES - 1 < KTILES) {
            load_stage_at(psOff, gAp, gBp);
            gAp += BK; gBp += BK;
        }
        asm volatile("cp.async.commit_group;" ::: "memory");

        // advance stage offsets with wrap (no % / mul)
        psOff += STAGE_BYTES; if (psOff == STAGES * STAGE_BYTES) psOff = 0;
        csOff += STAGE_BYTES; if (csOff == STAGES * STAGE_BYTES) csOff = 0;

#pragma unroll
        for (int ks = 0; ks < 4; ++ks) {           // 4 x k16 = BK 64
            const int cur = ks & 1;
            if (ks < 3) load_frags(cur ^ 1, sA, sB, (uint32_t)((ks + 1) * 32));
#pragma unroll
            for (int mt = 0; mt < 4; ++mt)
#pragma unroll
                for (int nt = 0; nt < 8; ++nt)
                    mma_f16(acc[mt][nt], afr[cur] + 4 * mt,
                            bfr[cur][2 * nt], bfr[cur][2 * nt + 1]);
        }
    }

    // ---- epilogue: add bias, store fp32 ----
    const int obase_n = ntile * BN + warp_n * 64;
    float bv0[8], bv1[8];
#pragma unroll
    for (int nt = 0; nt < 8; ++nt) {
        int col = obase_n + nt * 8 + (lane & 3) * 2;
        bv0[nt] = __ldg(bias + col);
        bv1[nt] = __ldg(bias + col + 1);
    }
#pragma unroll
    for (int mt = 0; mt < 4; ++mt) {
        int row0 = mtile * BM + warp_m * 64 + mt * 16 + (lane >> 2);
#pragma unroll
        for (int nt = 0; nt < 8; ++nt) {
            int col = obase_n + nt * 8 + (lane & 3) * 2;
            float2 o0 = make_float2(acc[mt][nt][0] + bv0[nt], acc[mt][nt][1] + bv1[nt]);
            float2 o1 = make_float2(acc[mt][nt][2] + bv0[nt], acc[mt][nt][3] + bv1[nt]);
            *(float2*)(out + (size_t)row0 * DIM_N + col) = o0;
            *(float2*)(out + (size_t)(row0 + 8) * DIM_N + col) = o1;
        }
    }
}

// ================= launch =================
extern "C" void kernel_launch(void* const* d_in, const int* in_sizes, int n_in,
                              void* d_out, int out_size) {
    const float* x    = (const float*)d_in[0];   // [8192, 4096]
    const float* w    = (const float*)d_in[1];   // [4096, 4096]
    const float* bias = (const float*)d_in[2];   // [4096]
    float* out = (float*)d_out;                  // [8192, 4096]

    cudaFuncSetAttribute(k_gemm, cudaFuncAttributeMaxDynamicSharedMemorySize, GEMM_SMEM);

    const int xblocks = (int)((size_t)DIM_M * DIM_K / (1024 * 16));   // 2048
    k_colpart<<<dim3(DIM_K / 256, 32), 256>>>(w);     // launch 0
    k_quantx<<<1 + xblocks, 1024>>>(x);               // launch 1 (reduce+sort + x->fp16)
    k_wbinh<<<DIM_N, 256>>>(w);                       // launch 2
    k_gemm<<<dim3(DIM_N / BN, DIM_M / BM), 128, GEMM_SMEM>>>(bias, out);  // launch 3 (ncu slot)
}

// round 17
// speedup vs baseline: 1.0600x; 1.0214x over previous
#include <cuda_runtime.h>
#include <cuda_fp16.h>
#include <cstdint>
#include <cstddef>

#define DIM_K 4096      // in_features
#define DIM_N 4096      // out_features
#define DIM_M 8192      // B*S

// ---------------- scratch (static device arrays; no allocation) ----------------
__device__ __align__(256) float g_part[32 * DIM_K];      // column-norm partials (32 row groups)
__device__ __align__(256) float g_mask[DIM_K];           // 1.0 = binarized column
__device__ float g_nbin;
__device__ __align__(256) __half g_xh[(size_t)DIM_M * DIM_K];   // fp16 x
__device__ __align__(256) __half g_wh[(size_t)DIM_N * DIM_K];   // fp16 w_bin

__device__ __forceinline__ uint32_t smem_u32(const void* p) {
    uint32_t a;
    asm("{ .reg .u64 t; cvta.to.shared.u64 t, %1; cvt.u32.u64 %0, t; }" : "=r"(a) : "l"(p));
    return a;
}

// ================= preprocessing (unchanged) =================

// Column L1-norm partials: 32 row groups x 128 rows, ascending add order.
__global__ void k_colpart(const float* __restrict__ w) {
    int j  = blockIdx.x * 256 + threadIdx.x;
    int i0 = blockIdx.y * 128;
    const float* p = w + (size_t)i0 * DIM_K + j;
    float s = 0.f;
#pragma unroll 16
    for (int i = 0; i < 128; ++i) s += fabsf(p[(size_t)i * DIM_K]);
    g_part[blockIdx.y * DIM_K + j] = s;
}

// Fused: block 0 = partial reduction + bitonic sort + quantiles + mask + n_bin;
// blocks 1..2048 = x -> fp16 conversion (idle SMs do useful work).
__global__ void k_quantx(const float* __restrict__ x) {
    int t = threadIdx.x;  // 1024 threads

    if (blockIdx.x != 0) {
        size_t i0 = (((size_t)(blockIdx.x - 1) * 1024 + t) * 16);
#pragma unroll
        for (int u = 0; u < 4; ++u) {
            float4 v = *(const float4*)(x + i0 + u * 4);
            *(__half2*)(g_xh + i0 + u * 4)     = __floats2half2_rn(v.x, v.y);
            *(__half2*)(g_xh + i0 + u * 4 + 2) = __floats2half2_rn(v.z, v.w);
        }
        return;
    }

    __shared__ float s_sorted[DIM_K];
    __shared__ float s_lo, s_hi;
    __shared__ int s_cnt;
    float val[4];

#pragma unroll
    for (int c = 0; c < 4; ++c) {
        int j = c * 1024 + t;
        float v = 0.f;
#pragma unroll
        for (int p = 0; p < 32; ++p) v += g_part[p * DIM_K + j];
        val[c] = v;
        s_sorted[j] = v;
    }
    if (t == 0) s_cnt = 0;
    __syncthreads();

    for (int k = 2; k <= DIM_K; k <<= 1) {
        for (int jj = k >> 1; jj > 0; jj >>= 1) {
#pragma unroll
            for (int c = 0; c < 4; ++c) {
                int i = c * 1024 + t;
                int ixj = i ^ jj;
                if (ixj > i) {
                    float a = s_sorted[i], b = s_sorted[ixj];
                    bool up = ((i & k) == 0);
                    if ((a > b) == up) { s_sorted[i] = b; s_sorted[ixj] = a; }
                }
            }
            __syncthreads();
        }
    }

    if (t == 0) {
        // jnp.quantile 'linear': 0.05*4095 = 204.75; 0.95*4095 = 3890.25
        s_lo = s_sorted[204]  + 0.75f * (s_sorted[205]  - s_sorted[204]);
        s_hi = s_sorted[3890] + 0.25f * (s_sorted[3891] - s_sorted[3890]);
    }
    __syncthreads();

    int local = 0;
#pragma unroll
    for (int c = 0; c < 4; ++c) {
        int j = c * 1024 + t;
        float v = val[c];
        bool band = (v > s_lo) && (v < s_hi);   // middle band
        float m = band ? 0.f : 1.f;             // binarized = ~band
        g_mask[j] = m;
        local += (int)m;
    }
    atomicAdd(&s_cnt, local);
    __syncthreads();
    if (t == 0) g_nbin = (float)s_cnt;
}

// Per w-row: scale = sum(|w|*mask)/n_bin; o = mask ? w*scale : w; emit fp16.
__global__ void k_wbinh(const float* __restrict__ w) {
    __shared__ float red[256];
    __shared__ float s_scale;
    int r = blockIdx.x, t = threadIdx.x;
    const float* wr = w + (size_t)r * DIM_K;

    float4 v4[4];
#pragma unroll
    for (int c = 0; c < 4; ++c) v4[c] = *(const float4*)(wr + t * 4 + c * 1024);

    float s = 0.f;
#pragma unroll
    for (int c = 0; c < 4; ++c) {
        const float* f = (const float*)&v4[c];
#pragma unroll
        for (int e = 0; e < 4; ++e) s += fabsf(f[e]) * g_mask[t * 4 + c * 1024 + e];
    }
    red[t] = s; __syncthreads();
    for (int o = 128; o > 0; o >>= 1) { if (t < o) red[t] += red[t + o]; __syncthreads(); }
    if (t == 0) s_scale = red[0] / g_nbin;
    __syncthreads();
    float scale = s_scale;

#pragma unroll
    for (int c = 0; c < 4; ++c) {
        const float* f = (const float*)&v4[c];
        float o[4];
#pragma unroll
        for (int e = 0; e < 4; ++e) {
            int j = t * 4 + c * 1024 + e;
            o[e] = (g_mask[j] != 0.f) ? f[e] * scale : f[e];
        }
        size_t idx = (size_t)r * DIM_K + t * 4 + c * 1024;
        *(__half2*)(g_wh + idx)     = __floats2half2_rn(o[0], o[1]);
        *(__half2*)(g_wh + idx + 2) = __floats2half2_rn(o[2], o[3]);
    }
}

// ================= GEMM: out = x @ w_bin^T + bias (fp16 mma, f32 accum) =================
// CTA 128x128, 4 warps (2M x 2N), warp tile 64x64, BK=64 fp16 (=128B rows, SW128
// swizzle), 3-stage cp.async (wait_group 1), 2 CTAs/SM. Sync point moved between
// ks2 and ks3 so ks0 fragments of kt+1 are carried across the boundary and their
// ldmatrix latency overlaps ks3's MMA block.
#define BM 128
#define BN 128
#define BK 64
#define KTILES (DIM_K / BK)         // 64
#define STAGES 3
#define A_BYTES 16384               // 128 rows x 128B
#define B_BYTES 16384
#define STAGE_BYTES (A_BYTES + B_BYTES)
#define GEMM_SMEM (STAGES * STAGE_BYTES)

__device__ __forceinline__ void cp16(uint32_t dst, const void* src) {
    asm volatile("cp.async.cg.shared.global [%0], [%1], 16;" :: "r"(dst), "l"(src));
}
__device__ __forceinline__ void ldm_x4(uint32_t* r, uint32_t addr) {
    asm volatile("ldmatrix.sync.aligned.m8n8.x4.shared.b16 {%0,%1,%2,%3}, [%4];"
                 : "=r"(r[0]), "=r"(r[1]), "=r"(r[2]), "=r"(r[3]) : "r"(addr));
}
__device__ __forceinline__ void mma_f16(float* c, const uint32_t* a,
                                        uint32_t b0, uint32_t b1) {
    asm volatile(
        "mma.sync.aligned.m16n8k16.row.col.f32.f16.f16.f32 "
        "{%0,%1,%2,%3}, {%4,%5,%6,%7}, {%8,%9}, {%0,%1,%2,%3};"
        : "+f"(c[0]), "+f"(c[1]), "+f"(c[2]), "+f"(c[3])
        : "r"(a[0]), "r"(a[1]), "r"(a[2]), "r"(a[3]), "r"(b0), "r"(b1));
}

__global__ void __launch_bounds__(128, 2) k_gemm(
    const float* __restrict__ bias, float* __restrict__ out)
{
    extern __shared__ char smem[];
    const uint32_t sb = smem_u32(smem);
    const int tid = threadIdx.x;
    const int wid = tid >> 5;
    const int lane = tid & 31;
    const int warp_m = wid & 1;    // 0..1 -> M offset 64
    const int warp_n = wid >> 1;   // 0..1 -> N offset 64
    const int ntile = blockIdx.x;
    const int mtile = blockIdx.y;

    // loaders: 8 threads per 128B smem row (16B each); 128 threads -> 16 rows/pass,
    // 8 passes for each of A and B (128 rows each).
    const int lrow = tid >> 3;          // 0..15
    const int lc   = tid & 7;           // 16B chunk in row
    uint32_t swz[8];
#pragma unroll
    for (int p = 0; p < 8; ++p) {
        int row = lrow + p * 16;
        swz[p] = (uint32_t)(row * 128 + ((lc * 16) ^ ((row & 7) << 4)));
    }

    // incrementally advanced global pointers (thread-local row assignment baked in)
    const __half* gAp = g_xh + (size_t)mtile * BM * DIM_K + (size_t)lrow * DIM_K + lc * 8;
    const __half* gBp = g_wh + (size_t)ntile * BN * DIM_K + (size_t)lrow * DIM_K + lc * 8;

    // ldmatrix lane addressing
    const uint32_t sx = (uint32_t)((lane & 7) << 4);
    const int arow = warp_m * 64 + (lane & 15);                          // + mt*16
    const uint32_t acol16 = (lane & 16) ? 16u : 0u;
    const int brow = warp_n * 64 + (lane & 7) + ((lane & 16) ? 8 : 0);   // + h*16
    const uint32_t bcol16 = (lane & 8) ? 16u : 0u;

    float acc[4][8][4];
#pragma unroll
    for (int i = 0; i < 4; ++i)
#pragma unroll
        for (int j = 0; j < 8; ++j)
#pragma unroll
            for (int k = 0; k < 4; ++k) acc[i][j][k] = 0.f;

    auto load_stage_at = [&](uint32_t sOff, const __half* ga, const __half* gb) {
        uint32_t sA = sb + sOff;
        uint32_t sB = sA + A_BYTES;
#pragma unroll
        for (int p = 0; p < 8; ++p)
            cp16(sA + swz[p], ga + (size_t)(p * 16) * DIM_K);
#pragma unroll
        for (int p = 0; p < 8; ++p)
            cp16(sB + swz[p], gb + (size_t)(p * 16) * DIM_K);
    };

    // fragment double buffers
    uint32_t afr[2][16], bfr[2][16];
    auto load_frags = [&](int buf, uint32_t sA, uint32_t sB, uint32_t kcol) {
        const uint32_t bcol = kcol + bcol16;
        const uint32_t acol = kcol + acol16;
#pragma unroll
        for (int h = 0; h < 4; ++h)
            ldm_x4(bfr[buf] + 4 * h, sB + (uint32_t)((brow + h * 16) * 128) + (bcol ^ sx));
#pragma unroll
        for (int mt = 0; mt < 4; ++mt)
            ldm_x4(afr[buf] + 4 * mt, sA + (uint32_t)((arow + mt * 16) * 128) + (acol ^ sx));
    };

    auto mma_block = [&](int buf) {
#pragma unroll
        for (int mt = 0; mt < 4; ++mt)
#pragma unroll
            for (int nt = 0; nt < 8; ++nt)
                mma_f16(acc[mt][nt], afr[buf] + 4 * mt,
                        bfr[buf][2 * nt], bfr[buf][2 * nt + 1]);
    };

    // ---- prologue: prime stages 0 and 1; carry ks0 fragments of kt=0 ----
    load_stage_at(0, gAp, gBp);
    asm volatile("cp.async.commit_group;" ::: "memory");
    load_stage_at(STAGE_BYTES, gAp + BK, gBp + BK);
    asm volatile("cp.async.commit_group;" ::: "memory");
    gAp += 2 * BK; gBp += 2 * BK;                 // next prefetch kt = 2

    asm volatile("cp.async.wait_group 1;" ::: "memory");   // stage 0 resident
    __syncthreads();

    uint32_t csOff = 0;                           // compute stage smem offset
    uint32_t psOff = 2 * STAGE_BYTES;             // prefetch stage smem offset
    load_frags(0, sb, sb + A_BYTES, 0);           // kt=0 ks0 fragments

    for (int kt = 0; kt < KTILES; ++kt) {
        const uint32_t sA = sb + csOff;
        const uint32_t sB = sA + A_BYTES;

        // prefetch stage kt+2 (overwrites the stage whose reads finished before
        // the PREVIOUS iteration's barrier)
        if (kt + 2 < KTILES) {
            load_stage_at(psOff, gAp, gBp);
            gAp += BK; gBp += BK;
        }
        asm volatile("cp.async.commit_group;" ::: "memory");
        psOff += STAGE_BYTES; if (psOff == STAGES * STAGE_BYTES) psOff = 0;

        // ks = 0..2: fragment prefetch + MMA
#pragma unroll
        for (int ks = 0; ks < 3; ++ks) {
            const int cur = ks & 1;
            load_frags(cur ^ 1, sA, sB, (uint32_t)((ks + 1) * 32));
            mma_block(cur);
        }

        // boundary: make stage kt+1 visible to all threads; then carry its ks0
        // fragments into buf 0 while ks3's MMAs (buf 1) execute.
        asm volatile("cp.async.wait_group 1;" ::: "memory");
        __syncthreads();
        csOff += STAGE_BYTES; if (csOff == STAGES * STAGE_BYTES) csOff = 0;

        if (kt + 1 < KTILES)
            load_frags(0, sb + csOff, sb + csOff + A_BYTES, 0);
        mma_block(1);   // ks=3
    }

    // ---- epilogue: add bias, store fp32 ----
    const int obase_n = ntile * BN + warp_n * 64;
    float bv0[8], bv1[8];
#pragma unroll
    for (int nt = 0; nt < 8; ++nt) {
        int col = obase_n + nt * 8 + (lane & 3) * 2;
        bv0[nt] = __ldg(bias + col);
        bv1[nt] = __ldg(bias + col + 1);
    }
#pragma unroll
    for (int mt = 0; mt < 4; ++mt) {
        int row0 = mtile * BM + warp_m * 64 + mt * 16 + (lane >> 2);
#pragma unroll
        for (int nt = 0; nt < 8; ++nt) {
            int col = obase_n + nt * 8 + (lane & 3) * 2;
            float2 o0 = make_float2(acc[mt][nt][0] + bv0[nt], acc[mt][nt][1] + bv1[nt]);
            float2 o1 = make_float2(acc[mt][nt][2] + bv0[nt], acc[mt][nt][3] + bv1[nt]);
            *(float2*)(out + (size_t)row0 * DIM_N + col) = o0;
            *(float2*)(out + (size_t)(row0 + 8) * DIM_N + col) = o1;
        }
    }
}

// ================= launch =================
extern "C" void kernel_launch(void* const* d_in, const int* in_sizes, int n_in,
                              void* d_out, int out_size) {
    const float* x    = (const float*)d_in[0];   // [8192, 4096]
    const float* w    = (const float*)d_in[1];   // [4096, 4096]
    const float* bias = (const float*)d_in[2];   // [4096]
    float* out = (float*)d_out;                  // [8192, 4096]

    cudaFuncSetAttribute(k_gemm, cudaFuncAttributeMaxDynamicSharedMemorySize, GEMM_SMEM);

    const int xblocks = (int)((size_t)DIM_M * DIM_K / (1024 * 16));   // 2048
    k_colpart<<<dim3(DIM_K / 256, 32), 256>>>(w);     // launch 0
    k_quantx<<<1 + xblocks, 1024>>>(x);               // launch 1 (reduce+sort + x->fp16)
    k_wbinh<<<DIM_N, 256>>>(w);                       // launch 2
    k_gemm<<<dim3(DIM_N / BN, DIM_M / BM), 128, GEMM_SMEM>>>(bias, out);  // launch 3 (ncu slot)
}